// round 1
// baseline (speedup 1.0000x reference)
#include <cuda_runtime.h>
#include <math.h>

#define NB   8
#define TT   4096
#define CC   768
#define HIDD 3072
#define MTOT (NB * TT)      /* 32768 */
#define ADA6 (6 * CC)       /* 4608  */

// ---------------- scratch (static device globals; allocation-free) ----------
__device__ float g_ada[NB * ADA6];                 // adaLN params (8, 4608)
__device__ float g_h  [(size_t)MTOT * CC];         // LN+mod output (reused)
__device__ float g_qkv[(size_t)MTOT * 3 * CC];     // qkv
__device__ float g_att[(size_t)MTOT * CC];         // attention out (pre-proj)
__device__ float g_tmp[(size_t)MTOT * CC];         // gated proj out (windowed order)
__device__ float g_x  [(size_t)MTOT * CC];         // x after MSA branch (seq order)
__device__ float g_hid[(size_t)MTOT * HIDD];       // MLP hidden

// ---------------- adaLN: ada = silu(c) @ ada_w^T + ada_b --------------------
__global__ void __launch_bounds__(128) ada_kernel(
    const float* __restrict__ c, const float* __restrict__ w,
    const float* __restrict__ b, float* __restrict__ ada)
{
    __shared__ float sc[CC];
    const int n = blockIdx.x, tid = threadIdx.x;
    for (int i = tid; i < CC; i += 128) {
        float x = c[n * CC + i];
        sc[i] = x / (1.0f + expf(-x));
    }
    __syncthreads();
    const int j = blockIdx.y * 128 + tid;
    const float* wr = w + (size_t)j * CC;
    float acc = b[j];
    #pragma unroll 8
    for (int k = 0; k < CC; k++) acc += sc[k] * wr[k];
    ada[n * ADA6 + j] = acc;
}

// ---------------- LN + modulate ---------------------------------------------
// MODE 0: gather from x_seq through (shift + window partition); ada sh=0, sc=CC
// MODE 1: direct from g_x (sequence order); ada sh=3CC, sc=4CC
template <int MODE>
__global__ void __launch_bounds__(256) ln_mod_kernel(
    const float* __restrict__ xin, const float* __restrict__ ada,
    float* __restrict__ out)
{
    const int m = blockIdx.x, tid = threadIdx.x;
    const int n = m >> 12;
    const float* xr;
    if (MODE == 0) {
        int rem = m & 4095, win = rem >> 6, t = rem & 63;
        int gh = ((win >> 3) << 3) + (t >> 3);
        int gw = ((win & 7) << 3) + (t & 7);
        int tseq = (((gh + 4) & 63) << 6) | ((gw + 4) & 63);
        xr = xin + ((size_t)n * TT + tseq) * CC;
    } else {
        xr = xin + (size_t)m * CC;
    }
    float v0 = xr[tid], v1 = xr[tid + 256], v2 = xr[tid + 512];
    __shared__ float rs[256], rq[256];
    rs[tid] = v0 + v1 + v2;
    rq[tid] = v0 * v0 + v1 * v1 + v2 * v2;
    __syncthreads();
    #pragma unroll
    for (int off = 128; off > 0; off >>= 1) {
        if (tid < off) { rs[tid] += rs[tid + off]; rq[tid] += rq[tid + off]; }
        __syncthreads();
    }
    const float mean = rs[0] * (1.0f / CC);
    const float var  = rq[0] * (1.0f / CC) - mean * mean;
    const float rstd = rsqrtf(var + 1e-6f);
    const float* shv = ada + n * ADA6 + (MODE == 0 ? 0 : 3 * CC);
    const float* scv = ada + n * ADA6 + (MODE == 0 ? CC : 4 * CC);
    const size_t ob = (size_t)m * CC;
    out[ob + tid      ] = (v0 - mean) * rstd * (1.0f + scv[tid      ]) + shv[tid      ];
    out[ob + tid + 256] = (v1 - mean) * rstd * (1.0f + scv[tid + 256]) + shv[tid + 256];
    out[ob + tid + 512] = (v2 - mean) * rstd * (1.0f + scv[tid + 512]) + shv[tid + 512];
}

// ---------------- SGEMM (NT): C[M,N] = A[M,K] @ B[N,K]^T + bias -------------
// EPI 0: plain. 1: gated (g_msa). 2: tanh-GELU. 3: resid + gate (g_mlp).
// M fixed = MTOT, tiles 128x128x8, 256 threads, 8x8 per thread.
template <int EPI>
__global__ void __launch_bounds__(256) sgemm_nt(
    const float* __restrict__ A, const float* __restrict__ B,
    const float* __restrict__ bias, float* __restrict__ C,
    int N, int K, const float* __restrict__ gate, const float* __restrict__ resid)
{
    __shared__ float As[8][128];
    __shared__ float Bs[8][128];
    const int tid = threadIdx.x;
    const int n0 = blockIdx.x * 128;
    const int m0 = blockIdx.y * 128;
    const int lr = tid >> 1;            // 0..127
    const int lc = (tid & 1) << 2;      // 0 or 4
    const float* Ap = A + (size_t)(m0 + lr) * K + lc;
    const float* Bp = B + (size_t)(n0 + lr) * K + lc;
    const int ty = tid >> 4, tx = tid & 15;

    float acc[8][8];
    #pragma unroll
    for (int i = 0; i < 8; i++)
        #pragma unroll
        for (int j = 0; j < 8; j++) acc[i][j] = 0.0f;

    for (int k0 = 0; k0 < K; k0 += 8) {
        float4 a4 = *(const float4*)(Ap + k0);
        float4 b4 = *(const float4*)(Bp + k0);
        __syncthreads();
        As[lc + 0][lr] = a4.x; As[lc + 1][lr] = a4.y;
        As[lc + 2][lr] = a4.z; As[lc + 3][lr] = a4.w;
        Bs[lc + 0][lr] = b4.x; Bs[lc + 1][lr] = b4.y;
        Bs[lc + 2][lr] = b4.z; Bs[lc + 3][lr] = b4.w;
        __syncthreads();
        #pragma unroll
        for (int kk = 0; kk < 8; kk++) {
            float a[8], b[8];
            *(float4*)(a)     = *(const float4*)(&As[kk][ty * 8]);
            *(float4*)(a + 4) = *(const float4*)(&As[kk][ty * 8 + 4]);
            *(float4*)(b)     = *(const float4*)(&Bs[kk][tx * 8]);
            *(float4*)(b + 4) = *(const float4*)(&Bs[kk][tx * 8 + 4]);
            #pragma unroll
            for (int i = 0; i < 8; i++)
                #pragma unroll
                for (int j = 0; j < 8; j++)
                    acc[i][j] += a[i] * b[j];
        }
    }

    const int batch = m0 >> 12;   // 4096 % 128 == 0 -> whole tile same batch
    #pragma unroll
    for (int i = 0; i < 8; i++) {
        const int m = m0 + ty * 8 + i;
        #pragma unroll
        for (int j = 0; j < 8; j += 4) {
            float4 v;
            float* pv = &v.x;
            #pragma unroll
            for (int q = 0; q < 4; q++) {
                const int n = n0 + tx * 8 + j + q;
                float val = acc[i][j + q] + bias[n];
                if (EPI == 2) {
                    float t = 0.7978845608028654f * (val + 0.044715f * val * val * val);
                    val = 0.5f * val * (1.0f + tanhf(t));
                } else if (EPI == 1) {
                    val *= gate[batch * ADA6 + n];
                } else if (EPI == 3) {
                    val = resid[(size_t)m * N + n] + gate[batch * ADA6 + n] * val;
                }
                pv[q] = val;
            }
            *(float4*)(&C[(size_t)m * N + n0 + tx * 8 + j]) = v;
        }
    }
}

// ---------------- window attention: one block per (window, head) ------------
// q,k,v are 64x64 fp32. smem = 3 * 16KB = 48KB exactly.
__global__ void __launch_bounds__(128) attn_kernel(
    const float* __restrict__ qkv, float* __restrict__ out)
{
    __shared__ float sqv[4096];  // q (transposed+swizzled), later v [c][d]
    __shared__ float sk [4096];  // k [c][d]
    __shared__ float ssT[4096];  // S transposed [c][r], later P^T
    const int b = blockIdx.x, hh = blockIdx.y;
    const int tid = threadIdx.x;
    const float* base = qkv + (size_t)b * 64 * (3 * CC) + hh * 64;

    // load q (scaled, transposed w/ swizzle) and k
    for (int e = tid; e < 4096; e += 128) {
        int r = e >> 6, d = e & 63;
        sqv[(d << 6) | ((r + d) & 63)] = base[(size_t)r * (3 * CC) + d] * 0.125f;
        sk[e] = base[(size_t)r * (3 * CC) + CC + d];
    }
    __syncthreads();

    // S[r][c] = q[r]·k[c] : thread r = tid&63, c-half = (tid>>6)*32
    {
        const int r = tid & 63;
        const int ch = (tid >> 6) << 5;
        float accS[32];
        #pragma unroll
        for (int i = 0; i < 32; i++) accS[i] = 0.0f;
        for (int d0 = 0; d0 < 64; d0 += 8) {
            float qr[8];
            #pragma unroll
            for (int dd = 0; dd < 8; dd++) {
                int d = d0 + dd;
                qr[dd] = sqv[(d << 6) | ((r + d) & 63)];
            }
            #pragma unroll
            for (int cc = 0; cc < 32; cc++) {
                const float* kr = &sk[(ch + cc) << 6];
                #pragma unroll
                for (int dd = 0; dd < 8; dd++)
                    accS[cc] += qr[dd] * kr[d0 + dd];
            }
        }
        #pragma unroll
        for (int cc = 0; cc < 32; cc++)
            ssT[((ch + cc) << 6) | r] = accS[cc];
    }
    __syncthreads();

    // softmax over c for row r = tid (lanes read consecutive r -> conflict-free)
    if (tid < 64) {
        const int r = tid;
        float mx = -1e30f;
        #pragma unroll
        for (int cI = 0; cI < 64; cI++) mx = fmaxf(mx, ssT[(cI << 6) | r]);
        float sum = 0.0f;
        #pragma unroll
        for (int cI = 0; cI < 64; cI++) {
            float e = __expf(ssT[(cI << 6) | r] - mx);
            ssT[(cI << 6) | r] = e;
            sum += e;
        }
        const float inv = 1.0f / sum;
        #pragma unroll
        for (int cI = 0; cI < 64; cI++) ssT[(cI << 6) | r] *= inv;
    }
    __syncthreads();

    // load v into sqv (plain [c][d])
    for (int e = tid; e < 4096; e += 128) {
        int r = e >> 6, d = e & 63;
        sqv[e] = base[(size_t)r * (3 * CC) + 2 * CC + d];
    }
    __syncthreads();

    // O[r][d] = sum_c P[r][c] v[c][d] : thread d = tid&63, r-half = (tid>>6)*32
    {
        const int d = tid & 63;
        const int rh = (tid >> 6) << 5;
        float accO[32];
        #pragma unroll
        for (int i = 0; i < 32; i++) accO[i] = 0.0f;
        for (int cI = 0; cI < 64; cI++) {
            const float vv = sqv[(cI << 6) | d];
            #pragma unroll
            for (int rr = 0; rr < 32; rr++)
                accO[rr] += ssT[(cI << 6) | (rh + rr)] * vv;
        }
        #pragma unroll
        for (int rr = 0; rr < 32; rr++)
            out[((size_t)b * 64 + rh + rr) * CC + hh * 64 + d] = accO[rr];
    }
}

// ---------------- residual + window-unpartition + inverse shift -------------
// x_final[n, tseq, :] = x_seq[n, tseq, :] + gated_proj[m_win, :]
__global__ void __launch_bounds__(256) scatter_kernel(
    const float* __restrict__ x_seq, const float* __restrict__ proj,
    float* __restrict__ xo)
{
    const int idx = blockIdx.x * 256 + threadIdx.x;
    if (idx >= MTOT * (CC / 4)) return;
    const int m = idx / (CC / 4);
    const int c4 = (idx - m * (CC / 4)) << 2;
    const int n = m >> 12, rem = m & 4095, win = rem >> 6, t = rem & 63;
    const int gh = ((win >> 3) << 3) + (t >> 3);
    const int gw = ((win & 7) << 3) + (t & 7);
    const int tseq = (((gh + 4) & 63) << 6) | ((gw + 4) & 63);
    const size_t so = ((size_t)n * TT + tseq) * CC + c4;
    float4 a = *(const float4*)(x_seq + so);
    float4 p = *(const float4*)(proj + (size_t)m * CC + c4);
    a.x += p.x; a.y += p.y; a.z += p.z; a.w += p.w;
    *(float4*)(xo + so) = a;
}

// ---------------- launch ------------------------------------------------------
extern "C" void kernel_launch(void* const* d_in, const int* in_sizes, int n_in,
                              void* d_out, int out_size)
{
    const float* x_seq  = (const float*)d_in[0];
    const float* c      = (const float*)d_in[1];
    const float* qkv_w  = (const float*)d_in[2];
    const float* qkv_b  = (const float*)d_in[3];
    const float* proj_w = (const float*)d_in[4];
    const float* proj_b = (const float*)d_in[5];
    const float* fc1_w  = (const float*)d_in[6];
    const float* fc1_b  = (const float*)d_in[7];
    const float* fc2_w  = (const float*)d_in[8];
    const float* fc2_b  = (const float*)d_in[9];
    const float* ada_w  = (const float*)d_in[10];
    const float* ada_b  = (const float*)d_in[11];
    float* out = (float*)d_out;

    float *ada, *h, *qkv, *att, *tmp, *x, *hid;
    cudaGetSymbolAddress((void**)&ada, g_ada);
    cudaGetSymbolAddress((void**)&h,   g_h);
    cudaGetSymbolAddress((void**)&qkv, g_qkv);
    cudaGetSymbolAddress((void**)&att, g_att);
    cudaGetSymbolAddress((void**)&tmp, g_tmp);
    cudaGetSymbolAddress((void**)&x,   g_x);
    cudaGetSymbolAddress((void**)&hid, g_hid);

    // 1) adaLN params
    ada_kernel<<<dim3(NB, ADA6 / 128), 128>>>(c, ada_w, ada_b, ada);
    // 2) gather + LN + modulate (MSA)
    ln_mod_kernel<0><<<MTOT, 256>>>(x_seq, ada, h);
    // 3) qkv GEMM
    sgemm_nt<0><<<dim3((3 * CC) / 128, MTOT / 128), 256>>>(
        h, qkv_w, qkv_b, qkv, 3 * CC, CC, nullptr, nullptr);
    // 4) window attention
    attn_kernel<<<dim3(MTOT / 64, 12), 128>>>(qkv, att);
    // 5) proj GEMM, gated by g_msa
    sgemm_nt<1><<<dim3(CC / 128, MTOT / 128), 256>>>(
        att, proj_w, proj_b, tmp, CC, CC, ada + 2 * CC, nullptr);
    // 6) residual + unpartition + unshift
    scatter_kernel<<<(MTOT * (CC / 4) + 255) / 256, 256>>>(x_seq, tmp, x);
    // 7) LN + modulate (MLP)
    ln_mod_kernel<1><<<MTOT, 256>>>(x, ada, h);
    // 8) fc1 GEMM + GELU
    sgemm_nt<2><<<dim3(HIDD / 128, MTOT / 128), 256>>>(
        h, fc1_w, fc1_b, hid, HIDD, CC, nullptr, nullptr);
    // 9) fc2 GEMM + residual + g_mlp gate -> d_out
    sgemm_nt<3><<<dim3(CC / 128, MTOT / 128), 256>>>(
        hid, fc2_w, fc2_b, out, CC, HIDD, ada + 5 * CC, x);
}

// round 3
// speedup vs baseline: 3.2920x; 3.2920x over previous
#include <cuda_runtime.h>
#include <math.h>
#include <stdint.h>

#define NB   8
#define TT   4096
#define CC   768
#define HIDD 3072
#define MTOT (NB * TT)      /* 32768 */
#define ADA6 (6 * CC)       /* 4608  */

// ---------------- scratch (static device globals; allocation-free) ----------
__device__ float g_ada[NB * ADA6];
__device__ float g_h  [(size_t)MTOT * CC];
__device__ float g_qkv[(size_t)MTOT * 3 * CC];
__device__ float g_att[(size_t)MTOT * CC];
__device__ float g_tmp[(size_t)MTOT * CC];
__device__ float g_x  [(size_t)MTOT * CC];
__device__ float g_hid[(size_t)MTOT * HIDD];
// tf32-rounded weights
__device__ float g_wq[3 * CC * CC];
__device__ float g_wp[CC * CC];
__device__ float g_w1[HIDD * CC];
__device__ float g_w2[CC * HIDD];

// ---------------- helpers ----------------------------------------------------
__device__ __forceinline__ uint32_t smem_u32(const void* p) {
    uint32_t a;
    asm("{ .reg .u64 t; cvta.to.shared.u64 t, %1; cvt.u32.u64 %0, t; }"
        : "=r"(a) : "l"(p));
    return a;
}

__device__ __forceinline__ float to_tf32(float x) {
    uint32_t u;
    asm("cvt.rna.tf32.f32 %0, %1;" : "=r"(u) : "f"(x));
    return __uint_as_float(u);
}

__device__ __forceinline__ void mma_tf32(float* d, const uint32_t* a, const uint32_t* b) {
    asm volatile(
        "mma.sync.aligned.m16n8k8.row.col.f32.tf32.tf32.f32 "
        "{%0,%1,%2,%3}, {%4,%5,%6,%7}, {%8,%9}, {%0,%1,%2,%3};"
        : "+f"(d[0]), "+f"(d[1]), "+f"(d[2]), "+f"(d[3])
        : "r"(a[0]), "r"(a[1]), "r"(a[2]), "r"(a[3]), "r"(b[0]), "r"(b[1]));
}

// ---------------- tf32 mma.sync GEMM (NT): C[M,N]=A[M,K]@B[N,K]^T + bias ----
// CTA tile 128x128x32, 3-stage cp.async, 8 warps (2x4), warp tile 64x32.
// EPI 0: plain. 1: gated (g_msa). 2: tanh-GELU + tf32 round. 3: resid + gate.
#define GPAD 36
#define STG_F (128 * GPAD)                 /* floats per tile per stage */
#define MM_SMEM_BYTES (6 * STG_F * 4)      /* 3 stages x (A+B) = 110592 */

template <int EPI>
__global__ void __launch_bounds__(256, 2) mm_gemm(
    const float* __restrict__ A, const float* __restrict__ B,
    const float* __restrict__ bias, float* __restrict__ C,
    int N, int K, const float* __restrict__ gate, const float* __restrict__ resid)
{
    extern __shared__ float sm[];
    const uint32_t smb = smem_u32(sm);
    const int tid = threadIdx.x;
    const int lane = tid & 31, wid = tid >> 5;
    const int g = lane >> 2, t4 = lane & 3;
    const int warpM = wid >> 2, warpN = wid & 3;
    const int n0 = blockIdx.x * 128, m0 = blockIdx.y * 128;
    const int nk = K >> 5;

    float acc[4][4][4];
    #pragma unroll
    for (int i = 0; i < 4; i++)
        #pragma unroll
        for (int j = 0; j < 4; j++)
            #pragma unroll
            for (int q = 0; q < 4; q++) acc[i][j][q] = 0.0f;

    auto load_stage = [&](int s, int kk) {
        const int k0 = kk << 5;
        #pragma unroll
        for (int j = 0; j < 4; j++) {
            const int f = tid + (j << 8);        // 0..1023
            const int r = f >> 3, q = f & 7;
            const float* srcA = A + (size_t)(m0 + r) * K + k0 + (q << 2);
            const float* srcB = B + (size_t)(n0 + r) * K + k0 + (q << 2);
            const uint32_t off = (uint32_t)(s * STG_F + r * GPAD + (q << 2)) << 2;
            asm volatile("cp.async.cg.shared.global [%0], [%1], 16;"
                         :: "r"(smb + off), "l"(srcA));
            asm volatile("cp.async.cg.shared.global [%0], [%1], 16;"
                         :: "r"(smb + (uint32_t)(3 * STG_F * 4) + off), "l"(srcB));
        }
        asm volatile("cp.async.commit_group;" ::: "memory");
    };

    load_stage(0, 0);
    load_stage(1, 1);

    int s = 0;
    for (int kk = 0; kk < nk; kk++) {
        if (kk + 1 < nk) asm volatile("cp.async.wait_group 1;" ::: "memory");
        else             asm volatile("cp.async.wait_group 0;" ::: "memory");
        __syncthreads();
        if (kk + 2 < nk) {
            int s2 = s + 2; if (s2 >= 3) s2 -= 3;
            load_stage(s2, kk + 2);
        }
        const float* Asb = sm + s * STG_F;
        const float* Bsb = sm + 3 * STG_F + s * STG_F;
        #pragma unroll
        for (int ks = 0; ks < 4; ks++) {
            const int k8 = ks << 3;
            uint32_t a[4][4], b[4][2];
            #pragma unroll
            for (int i = 0; i < 4; i++) {
                const int mb = warpM * 64 + i * 16;
                a[i][0] = __float_as_uint(Asb[(mb + g    ) * GPAD + k8 + t4    ]);
                a[i][1] = __float_as_uint(Asb[(mb + g + 8) * GPAD + k8 + t4    ]);
                a[i][2] = __float_as_uint(Asb[(mb + g    ) * GPAD + k8 + t4 + 4]);
                a[i][3] = __float_as_uint(Asb[(mb + g + 8) * GPAD + k8 + t4 + 4]);
            }
            #pragma unroll
            for (int j = 0; j < 4; j++) {
                const int nb = warpN * 32 + j * 8;
                b[j][0] = __float_as_uint(Bsb[(nb + g) * GPAD + k8 + t4    ]);
                b[j][1] = __float_as_uint(Bsb[(nb + g) * GPAD + k8 + t4 + 4]);
            }
            #pragma unroll
            for (int i = 0; i < 4; i++)
                #pragma unroll
                for (int j = 0; j < 4; j++)
                    mma_tf32(acc[i][j], a[i], b[j]);
        }
        if (++s == 3) s = 0;
    }

    // ---------------- epilogue ------------------------------------------------
    const int batch = m0 >> 12;
    const float* gbase = (EPI == 1 || EPI == 3) ? (gate + batch * ADA6) : nullptr;
    #pragma unroll
    for (int i = 0; i < 4; i++) {
        #pragma unroll
        for (int h2 = 0; h2 < 2; h2++) {
            const int row = m0 + warpM * 64 + i * 16 + g + h2 * 8;
            float* crow = C + (size_t)row * N;
            const float* rrow = (EPI == 3) ? (resid + (size_t)row * N) : nullptr;
            #pragma unroll
            for (int j = 0; j < 4; j++) {
                const int nc = n0 + warpN * 32 + j * 8 + t4 * 2;
                float v0 = acc[i][j][h2 * 2 + 0] + bias[nc];
                float v1 = acc[i][j][h2 * 2 + 1] + bias[nc + 1];
                if (EPI == 1) {
                    v0 *= gbase[nc]; v1 *= gbase[nc + 1];
                } else if (EPI == 2) {
                    float u0 = 0.7978845608028654f * (v0 + 0.044715f * v0 * v0 * v0);
                    float u1 = 0.7978845608028654f * (v1 + 0.044715f * v1 * v1 * v1);
                    v0 = to_tf32(__fdividef(v0, 1.0f + __expf(-2.0f * u0)));
                    v1 = to_tf32(__fdividef(v1, 1.0f + __expf(-2.0f * u1)));
                } else if (EPI == 3) {
                    v0 = rrow[nc] + gbase[nc] * v0;
                    v1 = rrow[nc + 1] + gbase[nc + 1] * v1;
                }
                *(float2*)(crow + nc) = make_float2(v0, v1);
            }
        }
    }
}

// ---------------- weight tf32 rounding ---------------------------------------
__global__ void __launch_bounds__(256) cvtw_kernel(
    const float* __restrict__ src, float* __restrict__ dst, int n4)
{
    const int i = blockIdx.x * 256 + threadIdx.x;
    if (i >= n4) return;
    float4 v = ((const float4*)src)[i];
    v.x = to_tf32(v.x); v.y = to_tf32(v.y);
    v.z = to_tf32(v.z); v.w = to_tf32(v.w);
    ((float4*)dst)[i] = v;
}

// ---------------- adaLN: ada = silu(c) @ ada_w^T + ada_b --------------------
__global__ void __launch_bounds__(128) ada_kernel(
    const float* __restrict__ c, const float* __restrict__ w,
    const float* __restrict__ b, float* __restrict__ ada)
{
    __shared__ float sc[CC];
    const int n = blockIdx.x, tid = threadIdx.x;
    for (int i = tid; i < CC; i += 128) {
        float x = c[n * CC + i];
        sc[i] = x / (1.0f + expf(-x));
    }
    __syncthreads();
    const int j = blockIdx.y * 128 + tid;
    const float* wr = w + (size_t)j * CC;
    float acc = b[j];
    #pragma unroll 8
    for (int k = 0; k < CC; k++) acc += sc[k] * wr[k];
    ada[n * ADA6 + j] = acc;
}

// ---------------- LN + modulate (output rounded to tf32) ---------------------
template <int MODE>
__global__ void __launch_bounds__(256) ln_mod_kernel(
    const float* __restrict__ xin, const float* __restrict__ ada,
    float* __restrict__ out)
{
    const int m = blockIdx.x, tid = threadIdx.x;
    const int n = m >> 12;
    const float* xr;
    if (MODE == 0) {
        int rem = m & 4095, win = rem >> 6, t = rem & 63;
        int gh = ((win >> 3) << 3) + (t >> 3);
        int gw = ((win & 7) << 3) + (t & 7);
        int tseq = (((gh + 4) & 63) << 6) | ((gw + 4) & 63);
        xr = xin + ((size_t)n * TT + tseq) * CC;
    } else {
        xr = xin + (size_t)m * CC;
    }
    float v0 = xr[tid], v1 = xr[tid + 256], v2 = xr[tid + 512];
    __shared__ float rs[256], rq[256];
    rs[tid] = v0 + v1 + v2;
    rq[tid] = v0 * v0 + v1 * v1 + v2 * v2;
    __syncthreads();
    #pragma unroll
    for (int off = 128; off > 0; off >>= 1) {
        if (tid < off) { rs[tid] += rs[tid + off]; rq[tid] += rq[tid + off]; }
        __syncthreads();
    }
    const float mean = rs[0] * (1.0f / CC);
    const float var  = rq[0] * (1.0f / CC) - mean * mean;
    const float rstd = rsqrtf(var + 1e-6f);
    const float* shv = ada + n * ADA6 + (MODE == 0 ? 0 : 3 * CC);
    const float* scv = ada + n * ADA6 + (MODE == 0 ? CC : 4 * CC);
    const size_t ob = (size_t)m * CC;
    out[ob + tid      ] = to_tf32((v0 - mean) * rstd * (1.0f + scv[tid      ]) + shv[tid      ]);
    out[ob + tid + 256] = to_tf32((v1 - mean) * rstd * (1.0f + scv[tid + 256]) + shv[tid + 256]);
    out[ob + tid + 512] = to_tf32((v2 - mean) * rstd * (1.0f + scv[tid + 512]) + shv[tid + 512]);
}

// ---------------- window attention: one block per (window, head) ------------
__global__ void __launch_bounds__(128) attn_kernel(
    const float* __restrict__ qkv, float* __restrict__ out)
{
    __shared__ float sqv[4096];
    __shared__ float sk [4096];
    __shared__ float ssT[4096];
    const int b = blockIdx.x, hh = blockIdx.y;
    const int tid = threadIdx.x;
    const float* base = qkv + (size_t)b * 64 * (3 * CC) + hh * 64;

    for (int e = tid; e < 4096; e += 128) {
        int r = e >> 6, d = e & 63;
        sqv[(d << 6) | ((r + d) & 63)] = base[(size_t)r * (3 * CC) + d] * 0.125f;
        sk[e] = base[(size_t)r * (3 * CC) + CC + d];
    }
    __syncthreads();

    {
        const int r = tid & 63;
        const int ch = (tid >> 6) << 5;
        float accS[32];
        #pragma unroll
        for (int i = 0; i < 32; i++) accS[i] = 0.0f;
        for (int d0 = 0; d0 < 64; d0 += 8) {
            float qr[8];
            #pragma unroll
            for (int dd = 0; dd < 8; dd++) {
                int d = d0 + dd;
                qr[dd] = sqv[(d << 6) | ((r + d) & 63)];
            }
            #pragma unroll
            for (int cc2 = 0; cc2 < 32; cc2++) {
                const float* kr = &sk[(ch + cc2) << 6];
                #pragma unroll
                for (int dd = 0; dd < 8; dd++)
                    accS[cc2] += qr[dd] * kr[d0 + dd];
            }
        }
        #pragma unroll
        for (int cc2 = 0; cc2 < 32; cc2++)
            ssT[((ch + cc2) << 6) | r] = accS[cc2];
    }
    __syncthreads();

    if (tid < 64) {
        const int r = tid;
        float mx = -1e30f;
        #pragma unroll
        for (int cI = 0; cI < 64; cI++) mx = fmaxf(mx, ssT[(cI << 6) | r]);
        float sum = 0.0f;
        #pragma unroll
        for (int cI = 0; cI < 64; cI++) {
            float e = __expf(ssT[(cI << 6) | r] - mx);
            ssT[(cI << 6) | r] = e;
            sum += e;
        }
        const float inv = 1.0f / sum;
        #pragma unroll
        for (int cI = 0; cI < 64; cI++) ssT[(cI << 6) | r] *= inv;
    }
    __syncthreads();

    for (int e = tid; e < 4096; e += 128) {
        int r = e >> 6, d = e & 63;
        sqv[e] = base[(size_t)r * (3 * CC) + 2 * CC + d];
    }
    __syncthreads();

    {
        const int d = tid & 63;
        const int rh = (tid >> 6) << 5;
        float accO[32];
        #pragma unroll
        for (int i = 0; i < 32; i++) accO[i] = 0.0f;
        for (int cI = 0; cI < 64; cI++) {
            const float vv = sqv[(cI << 6) | d];
            #pragma unroll
            for (int rr = 0; rr < 32; rr++)
                accO[rr] += ssT[(cI << 6) | (rh + rr)] * vv;
        }
        #pragma unroll
        for (int rr = 0; rr < 32; rr++)
            out[((size_t)b * 64 + rh + rr) * CC + hh * 64 + d] = to_tf32(accO[rr]);
    }
}

// ---------------- residual + window-unpartition + inverse shift -------------
__global__ void __launch_bounds__(256) scatter_kernel(
    const float* __restrict__ x_seq, const float* __restrict__ proj,
    float* __restrict__ xo)
{
    const int idx = blockIdx.x * 256 + threadIdx.x;
    if (idx >= MTOT * (CC / 4)) return;
    const int m = idx / (CC / 4);
    const int c4 = (idx - m * (CC / 4)) << 2;
    const int n = m >> 12, rem = m & 4095, win = rem >> 6, t = rem & 63;
    const int gh = ((win >> 3) << 3) + (t >> 3);
    const int gw = ((win & 7) << 3) + (t & 7);
    const int tseq = (((gh + 4) & 63) << 6) | ((gw + 4) & 63);
    const size_t so = ((size_t)n * TT + tseq) * CC + c4;
    float4 a = *(const float4*)(x_seq + so);
    float4 p = *(const float4*)(proj + (size_t)m * CC + c4);
    a.x += p.x; a.y += p.y; a.z += p.z; a.w += p.w;
    *(float4*)(xo + so) = a;
}

// ---------------- launch ------------------------------------------------------
extern "C" void kernel_launch(void* const* d_in, const int* in_sizes, int n_in,
                              void* d_out, int out_size)
{
    const float* x_seq  = (const float*)d_in[0];
    const float* c      = (const float*)d_in[1];
    const float* qkv_w  = (const float*)d_in[2];
    const float* qkv_b  = (const float*)d_in[3];
    const float* proj_w = (const float*)d_in[4];
    const float* proj_b = (const float*)d_in[5];
    const float* fc1_w  = (const float*)d_in[6];
    const float* fc1_b  = (const float*)d_in[7];
    const float* fc2_w  = (const float*)d_in[8];
    const float* fc2_b  = (const float*)d_in[9];
    const float* ada_w  = (const float*)d_in[10];
    const float* ada_b  = (const float*)d_in[11];
    float* out = (float*)d_out;

    float *ada, *h, *qkv, *att, *tmp, *x, *hid, *wq, *wp, *w1, *w2;
    cudaGetSymbolAddress((void**)&ada, g_ada);
    cudaGetSymbolAddress((void**)&h,   g_h);
    cudaGetSymbolAddress((void**)&qkv, g_qkv);
    cudaGetSymbolAddress((void**)&att, g_att);
    cudaGetSymbolAddress((void**)&tmp, g_tmp);
    cudaGetSymbolAddress((void**)&x,   g_x);
    cudaGetSymbolAddress((void**)&hid, g_hid);
    cudaGetSymbolAddress((void**)&wq,  g_wq);
    cudaGetSymbolAddress((void**)&wp,  g_wp);
    cudaGetSymbolAddress((void**)&w1,  g_w1);
    cudaGetSymbolAddress((void**)&w2,  g_w2);

    cudaFuncSetAttribute(mm_gemm<0>, cudaFuncAttributeMaxDynamicSharedMemorySize, MM_SMEM_BYTES);
    cudaFuncSetAttribute(mm_gemm<1>, cudaFuncAttributeMaxDynamicSharedMemorySize, MM_SMEM_BYTES);
    cudaFuncSetAttribute(mm_gemm<2>, cudaFuncAttributeMaxDynamicSharedMemorySize, MM_SMEM_BYTES);
    cudaFuncSetAttribute(mm_gemm<3>, cudaFuncAttributeMaxDynamicSharedMemorySize, MM_SMEM_BYTES);

    // 0) round weights to tf32 (rna)
    cvtw_kernel<<<(3 * CC * CC / 4 + 255) / 256, 256>>>(qkv_w, wq, 3 * CC * CC / 4);
    cvtw_kernel<<<(CC * CC / 4 + 255) / 256, 256>>>(proj_w, wp, CC * CC / 4);
    cvtw_kernel<<<(HIDD * CC / 4 + 255) / 256, 256>>>(fc1_w, w1, HIDD * CC / 4);
    cvtw_kernel<<<(CC * HIDD / 4 + 255) / 256, 256>>>(fc2_w, w2, CC * HIDD / 4);
    // 1) adaLN params
    ada_kernel<<<dim3(NB, ADA6 / 128), 128>>>(c, ada_w, ada_b, ada);
    // 2) gather + LN + modulate (MSA), tf32-rounded
    ln_mod_kernel<0><<<MTOT, 256>>>(x_seq, ada, h);
    // 3) qkv GEMM (mma.sync tf32)
    mm_gemm<0><<<dim3((3 * CC) / 128, MTOT / 128), 256, MM_SMEM_BYTES>>>(
        h, wq, qkv_b, qkv, 3 * CC, CC, nullptr, nullptr);
    // 4) window attention (fp32; output tf32-rounded)
    attn_kernel<<<dim3(MTOT / 64, 12), 128>>>(qkv, att);
    // 5) proj GEMM, gated by g_msa
    mm_gemm<1><<<dim3(CC / 128, MTOT / 128), 256, MM_SMEM_BYTES>>>(
        att, wp, proj_b, tmp, CC, CC, ada + 2 * CC, nullptr);
    // 6) residual + unpartition + unshift
    scatter_kernel<<<(MTOT * (CC / 4) + 255) / 256, 256>>>(x_seq, tmp, x);
    // 7) LN + modulate (MLP), tf32-rounded
    ln_mod_kernel<1><<<MTOT, 256>>>(x, ada, h);
    // 8) fc1 GEMM + GELU (+ tf32 round)
    mm_gemm<2><<<dim3(HIDD / 128, MTOT / 128), 256, MM_SMEM_BYTES>>>(
        h, w1, fc1_b, hid, HIDD, CC, nullptr, nullptr);
    // 9) fc2 GEMM + residual + g_mlp gate -> d_out
    mm_gemm<3><<<dim3(CC / 128, MTOT / 128), 256, MM_SMEM_BYTES>>>(
        hid, w2, fc2_b, out, CC, HIDD, ada + 5 * CC, x);
}

// round 4
// speedup vs baseline: 4.9074x; 1.4907x over previous
#include <cuda_runtime.h>
#include <cuda_bf16.h>
#include <math.h>
#include <stdint.h>

#define NB   8
#define TT   4096
#define CC   768
#define HIDD 3072
#define MTOT (NB * TT)      /* 32768 */
#define ADA6 (6 * CC)       /* 4608  */

// ---------------- scratch (static device globals; allocation-free) ----------
__device__ float g_ada[NB * ADA6];
__device__ float g_qkv[(size_t)MTOT * 3 * CC];
__device__ float g_tmp[(size_t)MTOT * CC];
__device__ float g_x  [(size_t)MTOT * CC];
__device__ __nv_bfloat16 g_hb  [(size_t)MTOT * CC];    // LN+mod output (bf16)
__device__ __nv_bfloat16 g_attb[(size_t)MTOT * CC];    // attention out (bf16)
__device__ __nv_bfloat16 g_hidb[(size_t)MTOT * HIDD];  // MLP hidden (bf16)
__device__ __nv_bfloat16 g_wqb[3 * CC * CC];
__device__ __nv_bfloat16 g_wpb[CC * CC];
__device__ __nv_bfloat16 g_w1b[HIDD * CC];
__device__ __nv_bfloat16 g_w2b[CC * HIDD];

// ---------------- helpers ----------------------------------------------------
__device__ __forceinline__ uint32_t smem_u32(const void* p) {
    uint32_t a;
    asm("{ .reg .u64 t; cvta.to.shared.u64 t, %1; cvt.u32.u64 %0, t; }"
        : "=r"(a) : "l"(p));
    return a;
}

__device__ __forceinline__ void mma_bf16(float* d, const uint32_t* a, const uint32_t* b) {
    asm volatile(
        "mma.sync.aligned.m16n8k16.row.col.f32.bf16.bf16.f32 "
        "{%0,%1,%2,%3}, {%4,%5,%6,%7}, {%8,%9}, {%0,%1,%2,%3};"
        : "+f"(d[0]), "+f"(d[1]), "+f"(d[2]), "+f"(d[3])
        : "r"(a[0]), "r"(a[1]), "r"(a[2]), "r"(a[3]), "r"(b[0]), "r"(b[1]));
}

// ---------------- bf16 mma.sync GEMM (NT): C[M,N]=A[M,K]@B[N,K]^T + bias ----
// CTA 128x128x32, 4-stage cp.async, 8 warps (2x4), warp tile 64x32.
// EPI 0: plain fp32. 1: gated fp32 (g_msa). 2: tanh-GELU -> bf16. 3: resid+gate fp32.
#define GSTRIDE 20                          /* u32 per row (16 data + 4 pad) */
#define STG_U   (128 * GSTRIDE)             /* u32 per tile per stage = 2560 */
#define NSTG    4
#define MM_SMEM_BYTES (2 * NSTG * STG_U * 4)  /* 81920 */

template <int EPI>
__global__ void __launch_bounds__(256, 2) mm_gemm(
    const __nv_bfloat16* __restrict__ A, const __nv_bfloat16* __restrict__ B,
    const float* __restrict__ bias, void* __restrict__ Cv,
    int N, int K, const float* __restrict__ gate, const float* __restrict__ resid)
{
    extern __shared__ uint32_t sm[];
    const uint32_t smb = smem_u32(sm);
    const uint32_t BOFF = NSTG * STG_U * 4;
    const int tid = threadIdx.x;
    const int lane = tid & 31, wid = tid >> 5;
    const int g = lane >> 2, t4 = lane & 3;
    const int warpM = wid >> 2, warpN = wid & 3;
    const int n0 = blockIdx.x * 128, m0 = blockIdx.y * 128;
    const int nk = K >> 5;

    float acc[4][4][4];
    #pragma unroll
    for (int i = 0; i < 4; i++)
        #pragma unroll
        for (int j = 0; j < 4; j++)
            #pragma unroll
            for (int q = 0; q < 4; q++) acc[i][j][q] = 0.0f;

    auto load_stage = [&](int s, int kk) {
        const int k0 = kk << 5;
        #pragma unroll
        for (int j = 0; j < 2; j++) {
            const int f = tid + (j << 8);        // 0..511
            const int r = f >> 2, q = f & 3;     // row, 16B quarter
            const __nv_bfloat16* srcA = A + (size_t)(m0 + r) * K + k0 + (q << 3);
            const __nv_bfloat16* srcB = B + (size_t)(n0 + r) * K + k0 + (q << 3);
            const uint32_t off = (uint32_t)(s * STG_U + r * GSTRIDE + (q << 2)) << 2;
            asm volatile("cp.async.cg.shared.global [%0], [%1], 16;"
                         :: "r"(smb + off), "l"(srcA));
            asm volatile("cp.async.cg.shared.global [%0], [%1], 16;"
                         :: "r"(smb + BOFF + off), "l"(srcB));
        }
        asm volatile("cp.async.commit_group;" ::: "memory");
    };

    load_stage(0, 0);
    load_stage(1, 1);
    load_stage(2, 2);

    int s = 0;
    for (int kk = 0; kk < nk; kk++) {
        if (kk + 1 < nk) asm volatile("cp.async.wait_group 2;" ::: "memory");
        else             asm volatile("cp.async.wait_group 0;" ::: "memory");
        __syncthreads();
        if (kk + 3 < nk) load_stage((s + 3) & 3, kk + 3);

        const uint32_t* Asb = sm + s * STG_U;
        const uint32_t* Bsb = sm + NSTG * STG_U + s * STG_U;
        #pragma unroll
        for (int ks = 0; ks < 2; ks++) {
            const int kc = ks << 3;              // u32 col base of k16 chunk
            uint32_t a[4][4], b[4][2];
            #pragma unroll
            for (int i = 0; i < 4; i++) {
                const int mb = warpM * 64 + i * 16;
                a[i][0] = Asb[(mb + g    ) * GSTRIDE + kc + t4    ];
                a[i][1] = Asb[(mb + g + 8) * GSTRIDE + kc + t4    ];
                a[i][2] = Asb[(mb + g    ) * GSTRIDE + kc + t4 + 4];
                a[i][3] = Asb[(mb + g + 8) * GSTRIDE + kc + t4 + 4];
            }
            #pragma unroll
            for (int j = 0; j < 4; j++) {
                const int nb = warpN * 32 + j * 8;
                b[j][0] = Bsb[(nb + g) * GSTRIDE + kc + t4    ];
                b[j][1] = Bsb[(nb + g) * GSTRIDE + kc + t4 + 4];
            }
            #pragma unroll
            for (int i = 0; i < 4; i++)
                #pragma unroll
                for (int j = 0; j < 4; j++)
                    mma_bf16(acc[i][j], a[i], b[j]);
        }
        s = (s + 1) & 3;
    }

    // ---------------- epilogue ------------------------------------------------
    const int batch = m0 >> 12;
    const float* gbase = (EPI == 1 || EPI == 3) ? (gate + batch * ADA6) : nullptr;
    #pragma unroll
    for (int i = 0; i < 4; i++) {
        #pragma unroll
        for (int h2 = 0; h2 < 2; h2++) {
            const int row = m0 + warpM * 64 + i * 16 + g + h2 * 8;
            const float* rrow = (EPI == 3) ? (resid + (size_t)row * N) : nullptr;
            #pragma unroll
            for (int j = 0; j < 4; j++) {
                const int nc = n0 + warpN * 32 + j * 8 + t4 * 2;
                float v0 = acc[i][j][h2 * 2 + 0] + bias[nc];
                float v1 = acc[i][j][h2 * 2 + 1] + bias[nc + 1];
                if (EPI == 1) {
                    v0 *= gbase[nc]; v1 *= gbase[nc + 1];
                } else if (EPI == 2) {
                    float u0 = 0.7978845608028654f * (v0 + 0.044715f * v0 * v0 * v0);
                    float u1 = 0.7978845608028654f * (v1 + 0.044715f * v1 * v1 * v1);
                    v0 = __fdividef(v0, 1.0f + __expf(-2.0f * u0));
                    v1 = __fdividef(v1, 1.0f + __expf(-2.0f * u1));
                } else if (EPI == 3) {
                    v0 = rrow[nc] + gbase[nc] * v0;
                    v1 = rrow[nc + 1] + gbase[nc + 1] * v1;
                }
                if (EPI == 2) {
                    __nv_bfloat16* crow = (__nv_bfloat16*)Cv + (size_t)row * N;
                    *(__nv_bfloat162*)(crow + nc) =
                        __floats2bfloat162_rn(v0, v1);
                } else {
                    float* crow = (float*)Cv + (size_t)row * N;
                    *(float2*)(crow + nc) = make_float2(v0, v1);
                }
            }
        }
    }
}

// ---------------- weight fp32 -> bf16 (rn) -----------------------------------
__global__ void __launch_bounds__(256) cvtw_kernel(
    const float* __restrict__ src, __nv_bfloat16* __restrict__ dst, int n4)
{
    const int i = blockIdx.x * 256 + threadIdx.x;
    if (i >= n4) return;
    float4 v = ((const float4*)src)[i];
    __nv_bfloat162 lo = __floats2bfloat162_rn(v.x, v.y);
    __nv_bfloat162 hi = __floats2bfloat162_rn(v.z, v.w);
    ((__nv_bfloat162*)dst)[i * 2]     = lo;
    ((__nv_bfloat162*)dst)[i * 2 + 1] = hi;
}

// ---------------- adaLN: ada = silu(c) @ ada_w^T + ada_b --------------------
__global__ void __launch_bounds__(128) ada_kernel(
    const float* __restrict__ c, const float* __restrict__ w,
    const float* __restrict__ b, float* __restrict__ ada)
{
    __shared__ float sc[CC];
    const int n = blockIdx.x, tid = threadIdx.x;
    for (int i = tid; i < CC; i += 128) {
        float x = c[n * CC + i];
        sc[i] = x / (1.0f + expf(-x));
    }
    __syncthreads();
    const int j = blockIdx.y * 128 + tid;
    const float* wr = w + (size_t)j * CC;
    float acc = b[j];
    #pragma unroll 8
    for (int k = 0; k < CC; k++) acc += sc[k] * wr[k];
    ada[n * ADA6 + j] = acc;
}

// ---------------- LN + modulate -> bf16 ---------------------------------------
template <int MODE>
__global__ void __launch_bounds__(256) ln_mod_kernel(
    const float* __restrict__ xin, const float* __restrict__ ada,
    __nv_bfloat16* __restrict__ out)
{
    const int m = blockIdx.x, tid = threadIdx.x;
    const int n = m >> 12;
    const float* xr;
    if (MODE == 0) {
        int rem = m & 4095, win = rem >> 6, t = rem & 63;
        int gh = ((win >> 3) << 3) + (t >> 3);
        int gw = ((win & 7) << 3) + (t & 7);
        int tseq = (((gh + 4) & 63) << 6) | ((gw + 4) & 63);
        xr = xin + ((size_t)n * TT + tseq) * CC;
    } else {
        xr = xin + (size_t)m * CC;
    }
    float v0 = xr[tid], v1 = xr[tid + 256], v2 = xr[tid + 512];
    __shared__ float rs[256], rq[256];
    rs[tid] = v0 + v1 + v2;
    rq[tid] = v0 * v0 + v1 * v1 + v2 * v2;
    __syncthreads();
    #pragma unroll
    for (int off = 128; off > 0; off >>= 1) {
        if (tid < off) { rs[tid] += rs[tid + off]; rq[tid] += rq[tid + off]; }
        __syncthreads();
    }
    const float mean = rs[0] * (1.0f / CC);
    const float var  = rq[0] * (1.0f / CC) - mean * mean;
    const float rstd = rsqrtf(var + 1e-6f);
    const float* shv = ada + n * ADA6 + (MODE == 0 ? 0 : 3 * CC);
    const float* scv = ada + n * ADA6 + (MODE == 0 ? CC : 4 * CC);
    const size_t ob = (size_t)m * CC;
    out[ob + tid      ] = __float2bfloat16_rn((v0 - mean) * rstd * (1.0f + scv[tid      ]) + shv[tid      ]);
    out[ob + tid + 256] = __float2bfloat16_rn((v1 - mean) * rstd * (1.0f + scv[tid + 256]) + shv[tid + 256]);
    out[ob + tid + 512] = __float2bfloat16_rn((v2 - mean) * rstd * (1.0f + scv[tid + 512]) + shv[tid + 512]);
}

// ---------------- window attention: one block per (window, head) ------------
__global__ void __launch_bounds__(128) attn_kernel(
    const float* __restrict__ qkv, __nv_bfloat16* __restrict__ out)
{
    __shared__ float sqv[4096];
    __shared__ float sk [4096];
    __shared__ float ssT[4096];
    const int b = blockIdx.x, hh = blockIdx.y;
    const int tid = threadIdx.x;
    const float* base = qkv + (size_t)b * 64 * (3 * CC) + hh * 64;

    for (int e = tid; e < 4096; e += 128) {
        int r = e >> 6, d = e & 63;
        sqv[(d << 6) | ((r + d) & 63)] = base[(size_t)r * (3 * CC) + d] * 0.125f;
        sk[e] = base[(size_t)r * (3 * CC) + CC + d];
    }
    __syncthreads();

    {
        const int r = tid & 63;
        const int ch = (tid >> 6) << 5;
        float accS[32];
        #pragma unroll
        for (int i = 0; i < 32; i++) accS[i] = 0.0f;
        for (int d0 = 0; d0 < 64; d0 += 8) {
            float qr[8];
            #pragma unroll
            for (int dd = 0; dd < 8; dd++) {
                int d = d0 + dd;
                qr[dd] = sqv[(d << 6) | ((r + d) & 63)];
            }
            #pragma unroll
            for (int cc2 = 0; cc2 < 32; cc2++) {
                const float* kr = &sk[(ch + cc2) << 6];
                #pragma unroll
                for (int dd = 0; dd < 8; dd++)
                    accS[cc2] += qr[dd] * kr[d0 + dd];
            }
        }
        #pragma unroll
        for (int cc2 = 0; cc2 < 32; cc2++)
            ssT[((ch + cc2) << 6) | r] = accS[cc2];
    }
    __syncthreads();

    if (tid < 64) {
        const int r = tid;
        float mx = -1e30f;
        #pragma unroll
        for (int cI = 0; cI < 64; cI++) mx = fmaxf(mx, ssT[(cI << 6) | r]);
        float sum = 0.0f;
        #pragma unroll
        for (int cI = 0; cI < 64; cI++) {
            float e = __expf(ssT[(cI << 6) | r] - mx);
            ssT[(cI << 6) | r] = e;
            sum += e;
        }
        const float inv = 1.0f / sum;
        #pragma unroll
        for (int cI = 0; cI < 64; cI++) ssT[(cI << 6) | r] *= inv;
    }
    __syncthreads();

    for (int e = tid; e < 4096; e += 128) {
        int r = e >> 6, d = e & 63;
        sqv[e] = base[(size_t)r * (3 * CC) + 2 * CC + d];
    }
    __syncthreads();

    {
        const int d = tid & 63;
        const int rh = (tid >> 6) << 5;
        float accO[32];
        #pragma unroll
        for (int i = 0; i < 32; i++) accO[i] = 0.0f;
        for (int cI = 0; cI < 64; cI++) {
            const float vv = sqv[(cI << 6) | d];
            #pragma unroll
            for (int rr = 0; rr < 32; rr++)
                accO[rr] += ssT[(cI << 6) | (rh + rr)] * vv;
        }
        #pragma unroll
        for (int rr = 0; rr < 32; rr++)
            out[((size_t)b * 64 + rh + rr) * CC + hh * 64 + d] =
                __float2bfloat16_rn(accO[rr]);
    }
}

// ---------------- residual + window-unpartition + inverse shift -------------
__global__ void __launch_bounds__(256) scatter_kernel(
    const float* __restrict__ x_seq, const float* __restrict__ proj,
    float* __restrict__ xo)
{
    const int idx = blockIdx.x * 256 + threadIdx.x;
    if (idx >= MTOT * (CC / 4)) return;
    const int m = idx / (CC / 4);
    const int c4 = (idx - m * (CC / 4)) << 2;
    const int n = m >> 12, rem = m & 4095, win = rem >> 6, t = rem & 63;
    const int gh = ((win >> 3) << 3) + (t >> 3);
    const int gw = ((win & 7) << 3) + (t & 7);
    const int tseq = (((gh + 4) & 63) << 6) | ((gw + 4) & 63);
    const size_t so = ((size_t)n * TT + tseq) * CC + c4;
    float4 a = *(const float4*)(x_seq + so);
    float4 p = *(const float4*)(proj + (size_t)m * CC + c4);
    a.x += p.x; a.y += p.y; a.z += p.z; a.w += p.w;
    *(float4*)(xo + so) = a;
}

// ---------------- launch ------------------------------------------------------
extern "C" void kernel_launch(void* const* d_in, const int* in_sizes, int n_in,
                              void* d_out, int out_size)
{
    const float* x_seq  = (const float*)d_in[0];
    const float* c      = (const float*)d_in[1];
    const float* qkv_w  = (const float*)d_in[2];
    const float* qkv_b  = (const float*)d_in[3];
    const float* proj_w = (const float*)d_in[4];
    const float* proj_b = (const float*)d_in[5];
    const float* fc1_w  = (const float*)d_in[6];
    const float* fc1_b  = (const float*)d_in[7];
    const float* fc2_w  = (const float*)d_in[8];
    const float* fc2_b  = (const float*)d_in[9];
    const float* ada_w  = (const float*)d_in[10];
    const float* ada_b  = (const float*)d_in[11];
    float* out = (float*)d_out;

    float *ada, *qkv, *tmp, *x;
    __nv_bfloat16 *hb, *attb, *hidb, *wqb, *wpb, *w1b, *w2b;
    cudaGetSymbolAddress((void**)&ada,  g_ada);
    cudaGetSymbolAddress((void**)&qkv,  g_qkv);
    cudaGetSymbolAddress((void**)&tmp,  g_tmp);
    cudaGetSymbolAddress((void**)&x,    g_x);
    cudaGetSymbolAddress((void**)&hb,   g_hb);
    cudaGetSymbolAddress((void**)&attb, g_attb);
    cudaGetSymbolAddress((void**)&hidb, g_hidb);
    cudaGetSymbolAddress((void**)&wqb,  g_wqb);
    cudaGetSymbolAddress((void**)&wpb,  g_wpb);
    cudaGetSymbolAddress((void**)&w1b,  g_w1b);
    cudaGetSymbolAddress((void**)&w2b,  g_w2b);

    cudaFuncSetAttribute(mm_gemm<0>, cudaFuncAttributeMaxDynamicSharedMemorySize, MM_SMEM_BYTES);
    cudaFuncSetAttribute(mm_gemm<1>, cudaFuncAttributeMaxDynamicSharedMemorySize, MM_SMEM_BYTES);
    cudaFuncSetAttribute(mm_gemm<2>, cudaFuncAttributeMaxDynamicSharedMemorySize, MM_SMEM_BYTES);
    cudaFuncSetAttribute(mm_gemm<3>, cudaFuncAttributeMaxDynamicSharedMemorySize, MM_SMEM_BYTES);

    // 0) weights -> bf16
    cvtw_kernel<<<(3 * CC * CC / 4 + 255) / 256, 256>>>(qkv_w, wqb, 3 * CC * CC / 4);
    cvtw_kernel<<<(CC * CC / 4 + 255) / 256, 256>>>(proj_w, wpb, CC * CC / 4);
    cvtw_kernel<<<(HIDD * CC / 4 + 255) / 256, 256>>>(fc1_w, w1b, HIDD * CC / 4);
    cvtw_kernel<<<(CC * HIDD / 4 + 255) / 256, 256>>>(fc2_w, w2b, CC * HIDD / 4);
    // 1) adaLN params
    ada_kernel<<<dim3(NB, ADA6 / 128), 128>>>(c, ada_w, ada_b, ada);
    // 2) gather + LN + modulate (MSA) -> bf16
    ln_mod_kernel<0><<<MTOT, 256>>>(x_seq, ada, hb);
    // 3) qkv GEMM (bf16 mma) -> fp32
    mm_gemm<0><<<dim3((3 * CC) / 128, MTOT / 128), 256, MM_SMEM_BYTES>>>(
        hb, wqb, qkv_b, qkv, 3 * CC, CC, nullptr, nullptr);
    // 4) window attention (fp32) -> bf16
    attn_kernel<<<dim3(MTOT / 64, 12), 128>>>(qkv, attb);
    // 5) proj GEMM, gated by g_msa -> fp32
    mm_gemm<1><<<dim3(CC / 128, MTOT / 128), 256, MM_SMEM_BYTES>>>(
        attb, wpb, proj_b, tmp, CC, CC, ada + 2 * CC, nullptr);
    // 6) residual + unpartition + unshift
    scatter_kernel<<<(MTOT * (CC / 4) + 255) / 256, 256>>>(x_seq, tmp, x);
    // 7) LN + modulate (MLP) -> bf16
    ln_mod_kernel<1><<<MTOT, 256>>>(x, ada, hb);
    // 8) fc1 GEMM + GELU -> bf16
    mm_gemm<2><<<dim3(HIDD / 128, MTOT / 128), 256, MM_SMEM_BYTES>>>(
        hb, w1b, fc1_b, hidb, HIDD, CC, nullptr, nullptr);
    // 9) fc2 GEMM + residual + g_mlp gate -> d_out (fp32)
    mm_gemm<3><<<dim3(CC / 128, MTOT / 128), 256, MM_SMEM_BYTES>>>(
        hidb, w2b, fc2_b, out, CC, HIDD, ada + 5 * CC, x);
}

// round 5
// speedup vs baseline: 5.4569x; 1.1120x over previous
#include <cuda_runtime.h>
#include <cuda_bf16.h>
#include <math.h>
#include <stdint.h>

#define NB   8
#define TT   4096
#define CC   768
#define HIDD 3072
#define MTOT (NB * TT)      /* 32768 */
#define ADA6 (6 * CC)       /* 4608  */

// ---------------- scratch (static device globals; allocation-free) ----------
__device__ float g_ada[NB * ADA6];
__device__ float g_x  [(size_t)MTOT * CC];
__device__ __nv_bfloat16 g_hb  [(size_t)MTOT * CC];     // LN+mod output (bf16)
__device__ __nv_bfloat16 g_qkvb[(size_t)MTOT * 3 * CC]; // qkv (bf16)
__device__ __nv_bfloat16 g_attb[(size_t)MTOT * CC];     // attention out (bf16)
__device__ __nv_bfloat16 g_hidb[(size_t)MTOT * HIDD];   // MLP hidden (bf16)
__device__ __nv_bfloat16 g_wqb[3 * CC * CC];
__device__ __nv_bfloat16 g_wpb[CC * CC];
__device__ __nv_bfloat16 g_w1b[HIDD * CC];
__device__ __nv_bfloat16 g_w2b[CC * HIDD];

// ---------------- helpers ----------------------------------------------------
__device__ __forceinline__ uint32_t smem_u32(const void* p) {
    uint32_t a;
    asm("{ .reg .u64 t; cvta.to.shared.u64 t, %1; cvt.u32.u64 %0, t; }"
        : "=r"(a) : "l"(p));
    return a;
}

__device__ __forceinline__ void mma_bf16(float* d, const uint32_t* a, const uint32_t* b) {
    asm volatile(
        "mma.sync.aligned.m16n8k16.row.col.f32.bf16.bf16.f32 "
        "{%0,%1,%2,%3}, {%4,%5,%6,%7}, {%8,%9}, {%0,%1,%2,%3};"
        : "+f"(d[0]), "+f"(d[1]), "+f"(d[2]), "+f"(d[3])
        : "r"(a[0]), "r"(a[1]), "r"(a[2]), "r"(a[3]), "r"(b[0]), "r"(b[1]));
}

__device__ __forceinline__ uint32_t packbf(float lo, float hi) {
    __nv_bfloat162 h = __floats2bfloat162_rn(lo, hi);
    return *(uint32_t*)&h;
}

// window(m) -> sequence row index (inverse shift + unpartition)
__device__ __forceinline__ int win2seq(int m) {
    const int nbat = m >> 12, rem = m & 4095, win = rem >> 6, t = rem & 63;
    const int gh = ((win >> 3) << 3) + (t >> 3);
    const int gw = ((win & 7) << 3) + (t & 7);
    return nbat * TT + ((((gh + 4) & 63) << 6) | ((gw + 4) & 63));
}

// ---------------- bf16 mma.sync GEMM (NT): C[M,N]=A[M,K]@B[N,K]^T + bias ----
// CTA 128x128x32, 4-stage cp.async, 8 warps (2x4), warp tile 64x32.
// EPI 0: -> bf16 (qkv). 1: gate + scatter-residual -> fp32 (proj).
// EPI 2: tanh-GELU -> bf16 (fc1). 3: resid + gate -> fp32 (fc2/out).
#define GSTRIDE 20
#define STG_U   (128 * GSTRIDE)
#define NSTG    4
#define MM_SMEM_BYTES (2 * NSTG * STG_U * 4)

template <int EPI>
__global__ void __launch_bounds__(256, 2) mm_gemm(
    const __nv_bfloat16* __restrict__ A, const __nv_bfloat16* __restrict__ B,
    const float* __restrict__ bias, void* __restrict__ Cv,
    int N, int K, const float* __restrict__ gate, const float* __restrict__ resid)
{
    extern __shared__ uint32_t sm[];
    const uint32_t smb = smem_u32(sm);
    const uint32_t BOFF = NSTG * STG_U * 4;
    const int tid = threadIdx.x;
    const int lane = tid & 31, wid = tid >> 5;
    const int g = lane >> 2, t4 = lane & 3;
    const int warpM = wid >> 2, warpN = wid & 3;
    const int n0 = blockIdx.x * 128, m0 = blockIdx.y * 128;
    const int nk = K >> 5;

    float acc[4][4][4];
    #pragma unroll
    for (int i = 0; i < 4; i++)
        #pragma unroll
        for (int j = 0; j < 4; j++)
            #pragma unroll
            for (int q = 0; q < 4; q++) acc[i][j][q] = 0.0f;

    auto load_stage = [&](int s, int kk) {
        const int k0 = kk << 5;
        #pragma unroll
        for (int j = 0; j < 2; j++) {
            const int f = tid + (j << 8);
            const int r = f >> 2, q = f & 3;
            const __nv_bfloat16* srcA = A + (size_t)(m0 + r) * K + k0 + (q << 3);
            const __nv_bfloat16* srcB = B + (size_t)(n0 + r) * K + k0 + (q << 3);
            const uint32_t off = (uint32_t)(s * STG_U + r * GSTRIDE + (q << 2)) << 2;
            asm volatile("cp.async.cg.shared.global [%0], [%1], 16;"
                         :: "r"(smb + off), "l"(srcA));
            asm volatile("cp.async.cg.shared.global [%0], [%1], 16;"
                         :: "r"(smb + BOFF + off), "l"(srcB));
        }
        asm volatile("cp.async.commit_group;" ::: "memory");
    };

    load_stage(0, 0);
    load_stage(1, 1);
    load_stage(2, 2);

    int s = 0;
    for (int kk = 0; kk < nk; kk++) {
        if (kk + 1 < nk) asm volatile("cp.async.wait_group 2;" ::: "memory");
        else             asm volatile("cp.async.wait_group 0;" ::: "memory");
        __syncthreads();
        if (kk + 3 < nk) load_stage((s + 3) & 3, kk + 3);

        const uint32_t* Asb = sm + s * STG_U;
        const uint32_t* Bsb = sm + NSTG * STG_U + s * STG_U;
        #pragma unroll
        for (int ks = 0; ks < 2; ks++) {
            const int kc = ks << 3;
            uint32_t a[4][4], b[4][2];
            #pragma unroll
            for (int i = 0; i < 4; i++) {
                const int mb = warpM * 64 + i * 16;
                a[i][0] = Asb[(mb + g    ) * GSTRIDE + kc + t4    ];
                a[i][1] = Asb[(mb + g + 8) * GSTRIDE + kc + t4    ];
                a[i][2] = Asb[(mb + g    ) * GSTRIDE + kc + t4 + 4];
                a[i][3] = Asb[(mb + g + 8) * GSTRIDE + kc + t4 + 4];
            }
            #pragma unroll
            for (int j = 0; j < 4; j++) {
                const int nb = warpN * 32 + j * 8;
                b[j][0] = Bsb[(nb + g) * GSTRIDE + kc + t4    ];
                b[j][1] = Bsb[(nb + g) * GSTRIDE + kc + t4 + 4];
            }
            #pragma unroll
            for (int i = 0; i < 4; i++)
                #pragma unroll
                for (int j = 0; j < 4; j++)
                    mma_bf16(acc[i][j], a[i], b[j]);
        }
        s = (s + 1) & 3;
    }

    // ---------------- epilogue ------------------------------------------------
    const int batch = m0 >> 12;
    const float* gbase = (EPI == 1 || EPI == 3) ? (gate + batch * ADA6) : nullptr;
    #pragma unroll
    for (int i = 0; i < 4; i++) {
        #pragma unroll
        for (int h2 = 0; h2 < 2; h2++) {
            const int row = m0 + warpM * 64 + i * 16 + g + h2 * 8;
            const int srow = (EPI == 1) ? win2seq(row) : row;
            const float* rrow = (EPI == 1 || EPI == 3)
                                ? (resid + (size_t)srow * N) : nullptr;
            #pragma unroll
            for (int j = 0; j < 4; j++) {
                const int nc = n0 + warpN * 32 + j * 8 + t4 * 2;
                float v0 = acc[i][j][h2 * 2 + 0] + bias[nc];
                float v1 = acc[i][j][h2 * 2 + 1] + bias[nc + 1];
                if (EPI == 1) {
                    // gate + residual (scattered read of x_seq)
                    v0 = rrow[nc]     + gbase[nc]     * v0;
                    v1 = rrow[nc + 1] + gbase[nc + 1] * v1;
                } else if (EPI == 2) {
                    float u0 = 0.7978845608028654f * (v0 + 0.044715f * v0 * v0 * v0);
                    float u1 = 0.7978845608028654f * (v1 + 0.044715f * v1 * v1 * v1);
                    v0 = __fdividef(v0, 1.0f + __expf(-2.0f * u0));
                    v1 = __fdividef(v1, 1.0f + __expf(-2.0f * u1));
                } else if (EPI == 3) {
                    v0 = rrow[nc]     + gbase[nc]     * v0;
                    v1 = rrow[nc + 1] + gbase[nc + 1] * v1;
                }
                if (EPI == 0 || EPI == 2) {
                    __nv_bfloat16* crow = (__nv_bfloat16*)Cv + (size_t)row * N;
                    __nv_bfloat162 h = __floats2bfloat162_rn(v0, v1);
                    *(__nv_bfloat162*)(crow + nc) = h;
                } else {
                    float* crow = (float*)Cv + (size_t)srow * N;
                    *(float2*)(crow + nc) = make_float2(v0, v1);
                }
            }
        }
    }
}

// ---------------- weight fp32 -> bf16 (rn) -----------------------------------
__global__ void __launch_bounds__(256) cvtw_kernel(
    const float* __restrict__ src, __nv_bfloat16* __restrict__ dst, int n4)
{
    const int i = blockIdx.x * 256 + threadIdx.x;
    if (i >= n4) return;
    float4 v = ((const float4*)src)[i];
    ((__nv_bfloat162*)dst)[i * 2]     = __floats2bfloat162_rn(v.x, v.y);
    ((__nv_bfloat162*)dst)[i * 2 + 1] = __floats2bfloat162_rn(v.z, v.w);
}

// ---------------- adaLN: ada = silu(c) @ ada_w^T + ada_b --------------------
__global__ void __launch_bounds__(128) ada_kernel(
    const float* __restrict__ c, const float* __restrict__ w,
    const float* __restrict__ b, float* __restrict__ ada)
{
    __shared__ float sc[CC];
    const int n = blockIdx.x, tid = threadIdx.x;
    for (int i = tid; i < CC; i += 128) {
        float x = c[n * CC + i];
        sc[i] = x / (1.0f + expf(-x));
    }
    __syncthreads();
    const int j = blockIdx.y * 128 + tid;
    const float* wr = w + (size_t)j * CC;
    float acc = b[j];
    #pragma unroll 8
    for (int k = 0; k < CC; k++) acc += sc[k] * wr[k];
    ada[n * ADA6 + j] = acc;
}

// ---------------- LN + modulate -> bf16 ---------------------------------------
template <int MODE>
__global__ void __launch_bounds__(256) ln_mod_kernel(
    const float* __restrict__ xin, const float* __restrict__ ada,
    __nv_bfloat16* __restrict__ out)
{
    const int m = blockIdx.x, tid = threadIdx.x;
    const int n = m >> 12;
    const float* xr;
    if (MODE == 0) {
        xr = xin + (size_t)win2seq(m) * CC;
    } else {
        xr = xin + (size_t)m * CC;
    }
    float v0 = xr[tid], v1 = xr[tid + 256], v2 = xr[tid + 512];
    __shared__ float rs[256], rq[256];
    rs[tid] = v0 + v1 + v2;
    rq[tid] = v0 * v0 + v1 * v1 + v2 * v2;
    __syncthreads();
    #pragma unroll
    for (int off = 128; off > 0; off >>= 1) {
        if (tid < off) { rs[tid] += rs[tid + off]; rq[tid] += rq[tid + off]; }
        __syncthreads();
    }
    const float mean = rs[0] * (1.0f / CC);
    const float var  = rq[0] * (1.0f / CC) - mean * mean;
    const float rstd = rsqrtf(var + 1e-6f);
    const float* shv = ada + n * ADA6 + (MODE == 0 ? 0 : 3 * CC);
    const float* scv = ada + n * ADA6 + (MODE == 0 ? CC : 4 * CC);
    const size_t ob = (size_t)m * CC;
    out[ob + tid      ] = __float2bfloat16_rn((v0 - mean) * rstd * (1.0f + scv[tid      ]) + shv[tid      ]);
    out[ob + tid + 256] = __float2bfloat16_rn((v1 - mean) * rstd * (1.0f + scv[tid + 256]) + shv[tid + 256]);
    out[ob + tid + 512] = __float2bfloat16_rn((v2 - mean) * rstd * (1.0f + scv[tid + 512]) + shv[tid + 512]);
}

// ---------------- window attention (bf16 mma.sync, flash-style) --------------
// One block = one (window, head). 128 threads = 4 warps; warp owns 16 q-rows.
#define APAD 72   /* halves per smem row: 36 u32 -> conflict-free quad loads */
__global__ void __launch_bounds__(128) attn_mma_kernel(
    const __nv_bfloat16* __restrict__ qkv, __nv_bfloat16* __restrict__ out)
{
    __shared__ __nv_bfloat16 sq [64 * APAD];
    __shared__ __nv_bfloat16 sk [64 * APAD];
    __shared__ __nv_bfloat16 svt[64 * APAD];   // V transposed: [d][c]
    const int b = blockIdx.x, hh = blockIdx.y;
    const int tid = threadIdx.x, lane = tid & 31, wid = tid >> 5;
    const int g = lane >> 2, t = lane & 3;
    const __nv_bfloat16* base = qkv + (size_t)b * 64 * (3 * CC) + hh * 64;

    // load q (scaled by 1/8), k, v^T
    {
        const int r = tid >> 1;
        const __nv_bfloat162 s8 = __floats2bfloat162_rn(0.125f, 0.125f);
        #pragma unroll
        for (int i = 0; i < 4; i++) {
            const int c0 = ((tid & 1) << 5) + (i << 3);
            uint4 vq = *(const uint4*)(base + (size_t)r * (3 * CC) + c0);
            __nv_bfloat162* pq = (__nv_bfloat162*)&vq;
            pq[0] = __hmul2(pq[0], s8); pq[1] = __hmul2(pq[1], s8);
            pq[2] = __hmul2(pq[2], s8); pq[3] = __hmul2(pq[3], s8);
            *(uint4*)(sq + r * APAD + c0) = vq;
            uint4 vk = *(const uint4*)(base + (size_t)r * (3 * CC) + CC + c0);
            *(uint4*)(sk + r * APAD + c0) = vk;
            uint4 vv = *(const uint4*)(base + (size_t)r * (3 * CC) + 2 * CC + c0);
            const __nv_bfloat16* hv = (const __nv_bfloat16*)&vv;
            #pragma unroll
            for (int q2 = 0; q2 < 8; q2++)
                svt[(c0 + q2) * APAD + r] = hv[q2];
        }
    }
    __syncthreads();

    const uint32_t* sq32 = (const uint32_t*)sq;
    const uint32_t* sk32 = (const uint32_t*)sk;
    const uint32_t* sv32 = (const uint32_t*)svt;
    const int mb = wid << 4;                   // warp's q-row base
    const int RS = APAD / 2;                   // u32 row stride = 36

    // ---- S = Q K^T (warp: m16 x n64 x k64) ----
    float accS[8][4];
    #pragma unroll
    for (int j = 0; j < 8; j++)
        #pragma unroll
        for (int q = 0; q < 4; q++) accS[j][q] = 0.0f;
    #pragma unroll
    for (int ks = 0; ks < 4; ks++) {
        const int kc = ks << 3;
        uint32_t a[4];
        a[0] = sq32[(mb + g    ) * RS + kc + t    ];
        a[1] = sq32[(mb + g + 8) * RS + kc + t    ];
        a[2] = sq32[(mb + g    ) * RS + kc + t + 4];
        a[3] = sq32[(mb + g + 8) * RS + kc + t + 4];
        #pragma unroll
        for (int j = 0; j < 8; j++) {
            uint32_t bb[2];
            bb[0] = sk32[((j << 3) + g) * RS + kc + t    ];
            bb[1] = sk32[((j << 3) + g) * RS + kc + t + 4];
            mma_bf16(accS[j], a, bb);
        }
    }

    // ---- softmax over c (rows g and g+8 of the warp tile) ----
    float mx0 = -1e30f, mx1 = -1e30f;
    #pragma unroll
    for (int j = 0; j < 8; j++) {
        mx0 = fmaxf(mx0, fmaxf(accS[j][0], accS[j][1]));
        mx1 = fmaxf(mx1, fmaxf(accS[j][2], accS[j][3]));
    }
    mx0 = fmaxf(mx0, __shfl_xor_sync(0xffffffffu, mx0, 1));
    mx0 = fmaxf(mx0, __shfl_xor_sync(0xffffffffu, mx0, 2));
    mx1 = fmaxf(mx1, __shfl_xor_sync(0xffffffffu, mx1, 1));
    mx1 = fmaxf(mx1, __shfl_xor_sync(0xffffffffu, mx1, 2));
    float sum0 = 0.0f, sum1 = 0.0f;
    #pragma unroll
    for (int j = 0; j < 8; j++) {
        accS[j][0] = __expf(accS[j][0] - mx0);
        accS[j][1] = __expf(accS[j][1] - mx0);
        accS[j][2] = __expf(accS[j][2] - mx1);
        accS[j][3] = __expf(accS[j][3] - mx1);
        sum0 += accS[j][0] + accS[j][1];
        sum1 += accS[j][2] + accS[j][3];
    }
    sum0 += __shfl_xor_sync(0xffffffffu, sum0, 1);
    sum0 += __shfl_xor_sync(0xffffffffu, sum0, 2);
    sum1 += __shfl_xor_sync(0xffffffffu, sum1, 1);
    sum1 += __shfl_xor_sync(0xffffffffu, sum1, 2);
    const float inv0 = 1.0f / sum0, inv1 = 1.0f / sum1;

    // pack P into A-fragments (unnormalized; normalize at the end)
    uint32_t pa[4][4];
    #pragma unroll
    for (int ks = 0; ks < 4; ks++) {
        pa[ks][0] = packbf(accS[2 * ks][0],     accS[2 * ks][1]);
        pa[ks][1] = packbf(accS[2 * ks][2],     accS[2 * ks][3]);
        pa[ks][2] = packbf(accS[2 * ks + 1][0], accS[2 * ks + 1][1]);
        pa[ks][3] = packbf(accS[2 * ks + 1][2], accS[2 * ks + 1][3]);
    }

    // ---- O = P V (warp: m16 x n64(d) x k64(c)) ----
    float accO[8][4];
    #pragma unroll
    for (int j = 0; j < 8; j++)
        #pragma unroll
        for (int q = 0; q < 4; q++) accO[j][q] = 0.0f;
    #pragma unroll
    for (int ks = 0; ks < 4; ks++) {
        const int kc = ks << 3;
        #pragma unroll
        for (int j = 0; j < 8; j++) {
            uint32_t bb[2];
            bb[0] = sv32[((j << 3) + g) * RS + kc + t    ];
            bb[1] = sv32[((j << 3) + g) * RS + kc + t + 4];
            mma_bf16(accO[j], pa[ks], bb);
        }
    }

    // ---- write O (normalized) as bf16 ----
    __nv_bfloat16* orow0 = out + ((size_t)b * 64 + mb + g    ) * CC + hh * 64;
    __nv_bfloat16* orow1 = out + ((size_t)b * 64 + mb + g + 8) * CC + hh * 64;
    #pragma unroll
    for (int j = 0; j < 8; j++) {
        const int dc = (j << 3) + (t << 1);
        *(uint32_t*)(orow0 + dc) = packbf(accO[j][0] * inv0, accO[j][1] * inv0);
        *(uint32_t*)(orow1 + dc) = packbf(accO[j][2] * inv1, accO[j][3] * inv1);
    }
}

// ---------------- launch ------------------------------------------------------
extern "C" void kernel_launch(void* const* d_in, const int* in_sizes, int n_in,
                              void* d_out, int out_size)
{
    const float* x_seq  = (const float*)d_in[0];
    const float* c      = (const float*)d_in[1];
    const float* qkv_w  = (const float*)d_in[2];
    const float* qkv_b  = (const float*)d_in[3];
    const float* proj_w = (const float*)d_in[4];
    const float* proj_b = (const float*)d_in[5];
    const float* fc1_w  = (const float*)d_in[6];
    const float* fc1_b  = (const float*)d_in[7];
    const float* fc2_w  = (const float*)d_in[8];
    const float* fc2_b  = (const float*)d_in[9];
    const float* ada_w  = (const float*)d_in[10];
    const float* ada_b  = (const float*)d_in[11];
    float* out = (float*)d_out;

    float *ada, *x;
    __nv_bfloat16 *hb, *qkvb, *attb, *hidb, *wqb, *wpb, *w1b, *w2b;
    cudaGetSymbolAddress((void**)&ada,  g_ada);
    cudaGetSymbolAddress((void**)&x,    g_x);
    cudaGetSymbolAddress((void**)&hb,   g_hb);
    cudaGetSymbolAddress((void**)&qkvb, g_qkvb);
    cudaGetSymbolAddress((void**)&attb, g_attb);
    cudaGetSymbolAddress((void**)&hidb, g_hidb);
    cudaGetSymbolAddress((void**)&wqb,  g_wqb);
    cudaGetSymbolAddress((void**)&wpb,  g_wpb);
    cudaGetSymbolAddress((void**)&w1b,  g_w1b);
    cudaGetSymbolAddress((void**)&w2b,  g_w2b);

    cudaFuncSetAttribute(mm_gemm<0>, cudaFuncAttributeMaxDynamicSharedMemorySize, MM_SMEM_BYTES);
    cudaFuncSetAttribute(mm_gemm<1>, cudaFuncAttributeMaxDynamicSharedMemorySize, MM_SMEM_BYTES);
    cudaFuncSetAttribute(mm_gemm<2>, cudaFuncAttributeMaxDynamicSharedMemorySize, MM_SMEM_BYTES);
    cudaFuncSetAttribute(mm_gemm<3>, cudaFuncAttributeMaxDynamicSharedMemorySize, MM_SMEM_BYTES);

    // 0) weights -> bf16
    cvtw_kernel<<<(3 * CC * CC / 4 + 255) / 256, 256>>>(qkv_w, wqb, 3 * CC * CC / 4);
    cvtw_kernel<<<(CC * CC / 4 + 255) / 256, 256>>>(proj_w, wpb, CC * CC / 4);
    cvtw_kernel<<<(HIDD * CC / 4 + 255) / 256, 256>>>(fc1_w, w1b, HIDD * CC / 4);
    cvtw_kernel<<<(CC * HIDD / 4 + 255) / 256, 256>>>(fc2_w, w2b, CC * HIDD / 4);
    // 1) adaLN params
    ada_kernel<<<dim3(NB, ADA6 / 128), 128>>>(c, ada_w, ada_b, ada);
    // 2) gather + LN + modulate (MSA) -> bf16
    ln_mod_kernel<0><<<MTOT, 256>>>(x_seq, ada, hb);
    // 3) qkv GEMM (bf16 mma) -> bf16
    mm_gemm<0><<<dim3((3 * CC) / 128, MTOT / 128), 256, MM_SMEM_BYTES>>>(
        hb, wqb, qkv_b, qkvb, 3 * CC, CC, nullptr, nullptr);
    // 4) window attention (bf16 mma) -> bf16
    attn_mma_kernel<<<dim3(MTOT / 64, 12), 128>>>(qkvb, attb);
    // 5) proj GEMM: gate + scattered residual -> g_x (seq order, fp32)
    mm_gemm<1><<<dim3(CC / 128, MTOT / 128), 256, MM_SMEM_BYTES>>>(
        attb, wpb, proj_b, x, CC, CC, ada + 2 * CC, x_seq);
    // 6) LN + modulate (MLP) -> bf16
    ln_mod_kernel<1><<<MTOT, 256>>>(x, ada, hb);
    // 7) fc1 GEMM + GELU -> bf16
    mm_gemm<2><<<dim3(HIDD / 128, MTOT / 128), 256, MM_SMEM_BYTES>>>(
        hb, w1b, fc1_b, hidb, HIDD, CC, nullptr, nullptr);
    // 8) fc2 GEMM + residual + g_mlp gate -> d_out (fp32)
    mm_gemm<3><<<dim3(CC / 128, MTOT / 128), 256, MM_SMEM_BYTES>>>(
        hidb, w2b, fc2_b, out, CC, HIDD, ada + 5 * CC, x);
}